// round 15
// baseline (speedup 1.0000x reference)
#include <cuda_runtime.h>
#include <cuda_fp16.h>

#define N_INST 200000
#define N_NETN 50000
#define NN     250000
#define NE     2000000
#define CAP    64          // CSR bucket capacity per node (max deg ~30 for this dataset)

// ---------------- device scratch (no runtime allocation allowed) ----------------
__device__ float   g_xf[(size_t)NN * 64];     // x_f = h @ Wf + bf (fp32, self term)
__device__ float   g_xr[(size_t)NN * 64];     // x_r = h @ Wr + br
__device__ __half2 g_yf[(size_t)NN * 32];     // relu(x_f) fp16 (gather payload)
__device__ __half2 g_yr[(size_t)NN * 32];     // relu(x_r) fp16
__device__ float   g_disf[NN], g_disr[NN];    // deg^-1/2
__device__ float   g_idegf[NN], g_idegr[NN];  // deg^-1
__device__ int     g_cntf[NN], g_cntr[NN];    // edge counts (row / col)
__device__ int     g_fillF[NN], g_fillR[NN];
__device__ int2    g_csrF[(size_t)NN * CAP];  // bucketed by col (fwd target)
__device__ int2    g_csrR[(size_t)NN * CAP];  // bucketed by row (rev target)

// ---------------- helpers ----------------
__device__ __forceinline__ float leaky(float v) { return fmaxf(v, 0.1f * v); }

__device__ __forceinline__ void ldsm4(unsigned& r0, unsigned& r1, unsigned& r2,
                                      unsigned& r3, unsigned a) {
    asm volatile("ldmatrix.sync.aligned.m8n8.x4.shared.b16 {%0,%1,%2,%3}, [%4];"
                 : "=r"(r0), "=r"(r1), "=r"(r2), "=r"(r3) : "r"(a));
}
__device__ __forceinline__ void ldsm4t(unsigned& r0, unsigned& r1, unsigned& r2,
                                       unsigned& r3, unsigned a) {
    asm volatile("ldmatrix.sync.aligned.m8n8.x4.trans.shared.b16 {%0,%1,%2,%3}, [%4];"
                 : "=r"(r0), "=r"(r1), "=r"(r2), "=r"(r3) : "r"(a));
}
__device__ __forceinline__ void mma16816(float* c, unsigned a0, unsigned a1,
                                         unsigned a2, unsigned a3,
                                         unsigned b0, unsigned b1) {
    asm volatile(
        "mma.sync.aligned.m16n8k16.row.col.f32.f16.f16.f32 "
        "{%0,%1,%2,%3}, {%4,%5,%6,%7}, {%8,%9}, {%0,%1,%2,%3};"
        : "+f"(c[0]), "+f"(c[1]), "+f"(c[2]), "+f"(c[3])
        : "r"(a0), "r"(a1), "r"(a2), "r"(a3), "r"(b0), "r"(b1));
}

// ---------------- degree counting ----------------
__global__ __launch_bounds__(256) void k_count(const int* __restrict__ ei) {
    int e = blockIdx.x * 256 + threadIdx.x;
    if (e >= NE) return;
    atomicAdd(&g_cntf[ei[e]], 1);
    atomicAdd(&g_cntr[ei[NE + e]], 1);
}

__global__ __launch_bounds__(256) void k_deg() {
    int n = blockIdx.x * 256 + threadIdx.x;
    if (n >= NN) return;
    float df = (float)g_cntf[n] + 1.0f;
    float dr = (float)g_cntr[n] + 1.0f;
    g_disf[n] = rsqrtf(df);
    g_disr[n] = rsqrtf(dr);
    g_idegf[n] = 1.0f / df;
    g_idegr[n] = 1.0f / dr;
}

// ---------------- bucketed CSR placement (no scans) ----------------
__global__ __launch_bounds__(256) void k_place(const int* __restrict__ ei) {
    int e = blockIdx.x * 256 + threadIdx.x;
    if (e >= NE) return;
    int a = __ldg(ei + e);
    int b = __ldg(ei + NE + e);
    float nf = __ldg(&g_disf[a]) * __ldg(&g_disf[b]);
    float nr = __ldg(&g_disr[b]) * __ldg(&g_disr[a]);
    int pf = (b << 6) + atomicAdd(&g_fillF[b], 1);
    g_csrF[pf] = make_int2(a, __float_as_int(nf));
    int pr = (a << 6) + atomicAdd(&g_fillR[a], 1);
    g_csrR[pr] = make_int2(b, __float_as_int(nr));
}

// ---------------- fused tensor-core instance encoder (16 -> 128 -> 64) ----------------
__global__ __launch_bounds__(128) void k_encI(
    const float* __restrict__ x,
    const float* __restrict__ W1, const float* __restrict__ b1,
    const float* __restrict__ W2, const float* __restrict__ b2,
    float* __restrict__ out)
{
    __shared__ float  xs[64 * 16];
    __shared__ float  W1s[16 * 128];
    __shared__ float  b1s[128];
    __shared__ __half sT[64 * 128];    // row 256 B, swizzle ((c*2)^((n&7)<<4))
    __shared__ __half sW2[128 * 64];   // row 128 B, swizzle ((o*2)^((k&7)<<4))
    int tid = threadIdx.x;
    int tb = blockIdx.x * 64;

#pragma unroll
    for (int i = 0; i < 2; i++)
        ((float4*)xs)[tid + i * 128] = ((const float4*)(x + (size_t)tb * 16))[tid + i * 128];
#pragma unroll
    for (int i = 0; i < 4; i++)
        ((float4*)W1s)[tid + i * 128] = ((const float4*)W1)[tid + i * 128];
    if (tid < 128) b1s[tid] = b1[tid];
    {
        int o2 = (tid & 31) * 2;
        int k0 = tid >> 5;
#pragma unroll
        for (int i = 0; i < 32; i++) {
            int k = k0 + i * 4;
            float2 v = *(const float2*)&W2[k * 64 + o2];
            *(__half2*)((char*)sW2 + k * 128 + ((o2 * 2) ^ ((k & 7) << 4))) =
                __float22half2_rn(v);
        }
    }
    __syncthreads();

    {
        int n = tid & 63;
        int jh = (tid >> 6) * 64;
        float xr[16];
#pragma unroll
        for (int k4 = 0; k4 < 16; k4 += 4) {
            float4 v = *(const float4*)&xs[n * 16 + k4];
            xr[k4] = v.x; xr[k4 + 1] = v.y; xr[k4 + 2] = v.z; xr[k4 + 3] = v.w;
        }
#pragma unroll
        for (int j4 = 0; j4 < 64; j4 += 4) {
            int j = jh + j4;
            float4 acc = *(const float4*)&b1s[j];
#pragma unroll
            for (int k = 0; k < 16; k++) {
                float4 w = *(const float4*)&W1s[k * 128 + j];
                acc.x += xr[k] * w.x; acc.y += xr[k] * w.y;
                acc.z += xr[k] * w.z; acc.w += xr[k] * w.w;
            }
            __half2 h0 = __float22half2_rn(make_float2(leaky(acc.x), leaky(acc.y)));
            __half2 h1 = __float22half2_rn(make_float2(leaky(acc.z), leaky(acc.w)));
            int byte = n * 256 + ((j * 2) ^ ((n & 7) << 4));
            *(uint2*)((char*)sT + byte) = make_uint2(*(unsigned*)&h0, *(unsigned*)&h1);
        }
    }
    __syncthreads();

    unsigned tBase = (unsigned)__cvta_generic_to_shared(sT);
    unsigned wBase = (unsigned)__cvta_generic_to_shared(sW2);
    int w = tid >> 5, lane = tid & 31;
    int bn = w * 16;
    int g = lane >> 3, r = lane & 7;
    int tr = lane >> 2, tc = lane & 3;
    float c[8][4];
#pragma unroll
    for (int j = 0; j < 8; j++)
#pragma unroll
        for (int q = 0; q < 4; q++) c[j][q] = 0.f;
#pragma unroll
    for (int ks = 0; ks < 8; ks++) {
        int mrow = bn + (g & 1) * 8 + r;
        int kc = ks * 16 + (g >> 1) * 8;
        unsigned a0, a1, a2, a3;
        ldsm4(a0, a1, a2, a3, tBase + mrow * 256 + ((kc * 2) ^ ((mrow & 7) << 4)));
        int kb = ks * 16 + (g & 1) * 8 + r;
        unsigned bofs = wBase + kb * 128;
#pragma unroll
        for (int otp = 0; otp < 4; otp++) {
            int oc = otp * 16 + (g >> 1) * 8;
            unsigned b0, b1_, b2_, b3;
            ldsm4t(b0, b1_, b2_, b3, bofs + ((oc * 2) ^ ((kb & 7) << 4)));
            mma16816(c[otp * 2],     a0, a1, a2, a3, b0, b1_);
            mma16816(c[otp * 2 + 1], a0, a1, a2, a3, b2_, b3);
        }
    }
    int n0 = tb + bn + tr;
    int n1 = n0 + 8;
#pragma unroll
    for (int j = 0; j < 8; j++) {
        int o = j * 8 + tc * 2;
        float2 bv = *(const float2*)&b2[o];
        float2 e0 = make_float2(leaky(c[j][0] + bv.x), leaky(c[j][1] + bv.y));
        float2 e1 = make_float2(leaky(c[j][2] + bv.x), leaky(c[j][3] + bv.y));
        *(float2*)&out[(size_t)n0 * 256 + o] = e0;
        *(float2*)&out[(size_t)n1 * 256 + o] = e1;
    }
}

// ---------------- fused tensor-core net encoder (8 -> 64 -> 64) ----------------
__global__ __launch_bounds__(128) void k_encN(
    const float* __restrict__ x,
    const float* __restrict__ W1, const float* __restrict__ b1,
    const float* __restrict__ W2, const float* __restrict__ b2,
    float* __restrict__ out)
{
    __shared__ float  xs[64 * 8];
    __shared__ float  W1s[8 * 64];
    __shared__ float  b1s[64];
    __shared__ __half sT[64 * 64];     // row 128 B
    __shared__ __half sW2[64 * 64];    // row 128 B
    int tid = threadIdx.x;
    int tb = blockIdx.x * 64;

    // clamped loads (last block overhangs)
#pragma unroll
    for (int i = 0; i < 4; i++) {
        int idx = tid + i * 128;
        size_t gidx = (size_t)tb * 8 + idx;
        size_t mx = (size_t)N_NETN * 8 - 1;
        xs[idx] = x[gidx <= mx ? gidx : mx];
    }
    if (tid < 128) ((float4*)W1s)[tid] = ((const float4*)W1)[tid];
    if (tid < 64) b1s[tid] = b1[tid];
    {
        int o2 = (tid & 31) * 2;
        int k0 = tid >> 5;
#pragma unroll
        for (int i = 0; i < 16; i++) {
            int k = k0 + i * 4;
            float2 v = *(const float2*)&W2[k * 64 + o2];
            *(__half2*)((char*)sW2 + k * 128 + ((o2 * 2) ^ ((k & 7) << 4))) =
                __float22half2_rn(v);
        }
    }
    __syncthreads();

    {
        int n = tid & 63;
        int jh = (tid >> 6) * 32;
        float xr[8];
#pragma unroll
        for (int k4 = 0; k4 < 8; k4 += 4) {
            float4 v = *(const float4*)&xs[n * 8 + k4];
            xr[k4] = v.x; xr[k4 + 1] = v.y; xr[k4 + 2] = v.z; xr[k4 + 3] = v.w;
        }
#pragma unroll
        for (int j4 = 0; j4 < 32; j4 += 4) {
            int j = jh + j4;
            float4 acc = *(const float4*)&b1s[j];
#pragma unroll
            for (int k = 0; k < 8; k++) {
                float4 w = *(const float4*)&W1s[k * 64 + j];
                acc.x += xr[k] * w.x; acc.y += xr[k] * w.y;
                acc.z += xr[k] * w.z; acc.w += xr[k] * w.w;
            }
            __half2 h0 = __float22half2_rn(make_float2(leaky(acc.x), leaky(acc.y)));
            __half2 h1 = __float22half2_rn(make_float2(leaky(acc.z), leaky(acc.w)));
            int byte = n * 128 + ((j * 2) ^ ((n & 7) << 4));
            *(uint2*)((char*)sT + byte) = make_uint2(*(unsigned*)&h0, *(unsigned*)&h1);
        }
    }
    __syncthreads();

    unsigned tBase = (unsigned)__cvta_generic_to_shared(sT);
    unsigned wBase = (unsigned)__cvta_generic_to_shared(sW2);
    int w = tid >> 5, lane = tid & 31;
    int bn = w * 16;
    int g = lane >> 3, r = lane & 7;
    int tr = lane >> 2, tc = lane & 3;
    float c[8][4];
#pragma unroll
    for (int j = 0; j < 8; j++)
#pragma unroll
        for (int q = 0; q < 4; q++) c[j][q] = 0.f;
#pragma unroll
    for (int ks = 0; ks < 4; ks++) {
        int mrow = bn + (g & 1) * 8 + r;
        int kc = ks * 16 + (g >> 1) * 8;
        unsigned a0, a1, a2, a3;
        ldsm4(a0, a1, a2, a3, tBase + mrow * 128 + ((kc * 2) ^ ((mrow & 7) << 4)));
        int kb = ks * 16 + (g & 1) * 8 + r;
        unsigned bofs = wBase + kb * 128;
#pragma unroll
        for (int otp = 0; otp < 4; otp++) {
            int oc = otp * 16 + (g >> 1) * 8;
            unsigned b0, b1_, b2_, b3;
            ldsm4t(b0, b1_, b2_, b3, bofs + ((oc * 2) ^ ((kb & 7) << 4)));
            mma16816(c[otp * 2],     a0, a1, a2, a3, b0, b1_);
            mma16816(c[otp * 2 + 1], a0, a1, a2, a3, b2_, b3);
        }
    }
    int n0 = tb + bn + tr;
    int n1 = n0 + 8;
#pragma unroll
    for (int j = 0; j < 8; j++) {
        int o = j * 8 + tc * 2;
        float2 bv = *(const float2*)&b2[o];
        float2 e0 = make_float2(leaky(c[j][0] + bv.x), leaky(c[j][1] + bv.y));
        float2 e1 = make_float2(leaky(c[j][2] + bv.x), leaky(c[j][3] + bv.y));
        if (n0 < N_NETN)
            *(float2*)&out[(size_t)(N_INST + n0) * 256 + o] = e0;
        if (n1 < N_NETN)
            *(float2*)&out[(size_t)(N_INST + n1) * 256 + o] = e1;
    }
}

// ---------------- tensor-core fused dual conv GEMM ----------------
__global__ __launch_bounds__(256) void k_mmt(
    const float* __restrict__ src, int srcOff,
    const float* __restrict__ Wf, const float* __restrict__ bf,
    const float* __restrict__ Wr, const float* __restrict__ br)
{
    __shared__ __half sA[128 * 64];
    __shared__ __half sW[2 * 64 * 64];
    int tid = threadIdx.x;
    int tb = blockIdx.x * 128;

    {
        int c2 = (tid & 31) * 2;
        int n0 = tid >> 5;
#pragma unroll
        for (int i = 0; i < 16; i++) {
            int n = n0 + i * 8;
            int g = tb + n; if (g >= NN) g = NN - 1;
            float2 v = *(const float2*)&src[(size_t)g * 256 + srcOff + c2];
            int byte = n * 128 + ((c2 * 2) ^ ((n & 7) << 4));
            *(__half2*)((char*)sA + byte) = __float22half2_rn(v);
        }
    }
    {
        int o2 = (tid & 31) * 2;
        int k0 = tid >> 5;
#pragma unroll
        for (int i = 0; i < 8; i++) {
            int k = k0 + i * 8;
            float2 vf = *(const float2*)&Wf[k * 64 + o2];
            float2 vr = *(const float2*)&Wr[k * 64 + o2];
            int sw = k * 128 + ((o2 * 2) ^ ((k & 7) << 4));
            *(__half2*)((char*)sW + sw) = __float22half2_rn(vf);
            *(__half2*)((char*)sW + 8192 + sw) = __float22half2_rn(vr);
        }
    }
    __syncthreads();

    unsigned aBase = (unsigned)__cvta_generic_to_shared(sA);
    unsigned wBase = (unsigned)__cvta_generic_to_shared(sW);
    int w = tid >> 5, lane = tid & 31;
    int bn = w * 16;
    int g = lane >> 3, r = lane & 7;
    int tr = lane >> 2, tc = lane & 3;

#pragma unroll
    for (int dir = 0; dir < 2; dir++) {
        const float* bias = dir ? br : bf;
        float*       dst  = dir ? g_xr : g_xf;
        __half2*     yout = dir ? g_yr : g_yf;
        float c[8][4];
#pragma unroll
        for (int j = 0; j < 8; j++)
#pragma unroll
            for (int q = 0; q < 4; q++) c[j][q] = 0.f;

#pragma unroll
        for (int ks = 0; ks < 4; ks++) {
            int mrow = bn + (g & 1) * 8 + r;
            int kc = ks * 16 + (g >> 1) * 8;
            unsigned a0, a1, a2, a3;
            ldsm4(a0, a1, a2, a3,
                  aBase + mrow * 128 + (((kc * 2)) ^ ((mrow & 7) << 4)));
            int kb = ks * 16 + (g & 1) * 8 + r;
            unsigned bofs = wBase + dir * 8192 + kb * 128;
#pragma unroll
            for (int otp = 0; otp < 4; otp++) {
                int oc = otp * 16 + (g >> 1) * 8;
                unsigned b0, b1, b2, b3;
                ldsm4t(b0, b1, b2, b3, bofs + ((oc * 2) ^ ((kb & 7) << 4)));
                mma16816(c[otp * 2],     a0, a1, a2, a3, b0, b1);
                mma16816(c[otp * 2 + 1], a0, a1, a2, a3, b2, b3);
            }
        }
        int n0 = tb + bn + tr;
        int n1 = n0 + 8;
#pragma unroll
        for (int j = 0; j < 8; j++) {
            int o = j * 8 + tc * 2;
            float2 bv = *(const float2*)&bias[o];
            float2 e0 = make_float2(c[j][0] + bv.x, c[j][1] + bv.y);
            float2 e1 = make_float2(c[j][2] + bv.x, c[j][3] + bv.y);
            if (n0 < NN) {
                *(float2*)&dst[(size_t)n0 * 64 + o] = e0;
                yout[(size_t)n0 * 32 + (o >> 1)] =
                    __float22half2_rn(make_float2(fmaxf(e0.x, 0.f), fmaxf(e0.y, 0.f)));
            }
            if (n1 < NN) {
                *(float2*)&dst[(size_t)n1 * 64 + o] = e1;
                yout[(size_t)n1 * 32 + (o >> 1)] =
                    __float22half2_rn(make_float2(fmaxf(e1.x, 0.f), fmaxf(e1.y, 0.f)));
            }
        }
    }
}

// ---------------- fused aggregation (bucketed CSR) + self terms + LN + leaky ----------------
__global__ __launch_bounds__(256) void k_agg(
    const float* __restrict__ rootf, const float* __restrict__ rootr,
    const float* __restrict__ lg, const float* __restrict__ lb,
    float* __restrict__ out, int off)
{
    int n = blockIdx.x * 8 + (threadIdx.x >> 5);
    int lane = threadIdx.x & 31;
    int d = lane * 2;
    int degF = g_cntr[n];
    int degR = g_cntf[n];
    float2 af = make_float2(0.f, 0.f);
    float2 ar = make_float2(0.f, 0.f);
    {
        const int2* cs = g_csrF + ((size_t)n << 6);
        const __half2* Y = g_yf;
        int i = 0;
        for (; i + 4 <= degF; i += 4) {
            int2 e0 = __ldg(cs + i), e1 = __ldg(cs + i + 1);
            int2 e2 = __ldg(cs + i + 2), e3 = __ldg(cs + i + 3);
            float2 v0 = __half22float2(__ldg(Y + (size_t)e0.x * 32 + lane));
            float2 v1 = __half22float2(__ldg(Y + (size_t)e1.x * 32 + lane));
            float2 v2 = __half22float2(__ldg(Y + (size_t)e2.x * 32 + lane));
            float2 v3 = __half22float2(__ldg(Y + (size_t)e3.x * 32 + lane));
            float n0 = __int_as_float(e0.y), n1 = __int_as_float(e1.y);
            float n2 = __int_as_float(e2.y), n3 = __int_as_float(e3.y);
            af.x += v0.x * n0 + v1.x * n1 + v2.x * n2 + v3.x * n3;
            af.y += v0.y * n0 + v1.y * n1 + v2.y * n2 + v3.y * n3;
        }
        for (; i < degF; i++) {
            int2 e0 = __ldg(cs + i);
            float2 v0 = __half22float2(__ldg(Y + (size_t)e0.x * 32 + lane));
            float n0 = __int_as_float(e0.y);
            af.x += v0.x * n0;
            af.y += v0.y * n0;
        }
    }
    {
        const int2* cs = g_csrR + ((size_t)n << 6);
        const __half2* Y = g_yr;
        int i = 0;
        for (; i + 4 <= degR; i += 4) {
            int2 e0 = __ldg(cs + i), e1 = __ldg(cs + i + 1);
            int2 e2 = __ldg(cs + i + 2), e3 = __ldg(cs + i + 3);
            float2 v0 = __half22float2(__ldg(Y + (size_t)e0.x * 32 + lane));
            float2 v1 = __half22float2(__ldg(Y + (size_t)e1.x * 32 + lane));
            float2 v2 = __half22float2(__ldg(Y + (size_t)e2.x * 32 + lane));
            float2 v3 = __half22float2(__ldg(Y + (size_t)e3.x * 32 + lane));
            float n0 = __int_as_float(e0.y), n1 = __int_as_float(e1.y);
            float n2 = __int_as_float(e2.y), n3 = __int_as_float(e3.y);
            ar.x += v0.x * n0 + v1.x * n1 + v2.x * n2 + v3.x * n3;
            ar.y += v0.y * n0 + v1.y * n1 + v2.y * n2 + v3.y * n3;
        }
        for (; i < degR; i++) {
            int2 e0 = __ldg(cs + i);
            float2 v0 = __half22float2(__ldg(Y + (size_t)e0.x * 32 + lane));
            float n0 = __int_as_float(e0.y);
            ar.x += v0.x * n0;
            ar.y += v0.y * n0;
        }
    }
    size_t o64 = (size_t)n * 64 + d;
    float2 fx = *(const float2*)&g_xf[o64];
    float2 rx = *(const float2*)&g_xr[o64];
    float idf = g_idegf[n], idr = g_idegr[n];
    float s0 = af.x + ar.x + fmaxf(fx.x + rootf[d], 0.f) * idf
                           + fmaxf(rx.x + rootr[d], 0.f) * idr;
    float s1 = af.y + ar.y + fmaxf(fx.y + rootf[d + 1], 0.f) * idf
                           + fmaxf(rx.y + rootr[d + 1], 0.f) * idr;
    float sum = s0 + s1;
#pragma unroll
    for (int o = 16; o > 0; o >>= 1) sum += __shfl_xor_sync(0xffffffffu, sum, o);
    float m = sum * (1.0f / 64.0f);
    float d0 = s0 - m, d1 = s1 - m;
    float sq = d0 * d0 + d1 * d1;
#pragma unroll
    for (int o = 16; o > 0; o >>= 1) sq += __shfl_xor_sync(0xffffffffu, sq, o);
    float inv = rsqrtf(sq * (1.0f / 64.0f) + 1e-5f);
    float o0 = leaky(d0 * inv * lg[d] + lb[d]);
    float o1 = leaky(d1 * inv * lg[d + 1] + lb[d + 1]);
    *(float2*)&out[(size_t)n * 256 + off + d] = make_float2(o0, o1);
}

// ---------------- launch ----------------
extern "C" void kernel_launch(void* const* d_in, const int* in_sizes, int n_in,
                              void* d_out, int out_size) {
    const float* x     = (const float*)d_in[0];
    const float* xnet  = (const float*)d_in[1];
    const int*   ei    = (const int*)  d_in[2];
    const float* e1W   = (const float*)d_in[3];
    const float* e1b   = (const float*)d_in[4];
    const float* e2W   = (const float*)d_in[5];
    const float* e2b   = (const float*)d_in[6];
    const float* n1W   = (const float*)d_in[7];
    const float* n1b   = (const float*)d_in[8];
    const float* n2W   = (const float*)d_in[9];
    const float* n2b   = (const float*)d_in[10];
    const float* convW = (const float*)d_in[11];
    const float* convb = (const float*)d_in[12];
    const float* convr = (const float*)d_in[13];
    const float* reW   = (const float*)d_in[14];
    const float* reb   = (const float*)d_in[15];
    const float* rer   = (const float*)d_in[16];
    const float* lng   = (const float*)d_in[17];
    const float* lnb   = (const float*)d_in[18];
    float* out = (float*)d_out;

    void *pcf, *pcr, *pff, *pfr;
    cudaGetSymbolAddress(&pcf, g_cntf);
    cudaGetSymbolAddress(&pcr, g_cntr);
    cudaGetSymbolAddress(&pff, g_fillF);
    cudaGetSymbolAddress(&pfr, g_fillR);

    static cudaStream_t s2 = []() {
        cudaStream_t s; cudaStreamCreateWithFlags(&s, cudaStreamNonBlocking); return s;
    }();
    auto mkev = []() { cudaEvent_t e; cudaEventCreateWithFlags(&e, cudaEventDisableTiming); return e; };
    static cudaEvent_t evF = mkev();
    static cudaEvent_t evCSR = mkev();

    cudaEventRecord(evF, 0);

    // ---- s2: bucketed CSR build (3 kernels, overlaps encoders) ----
    cudaStreamWaitEvent(s2, evF, 0);
    cudaMemsetAsync(pcf, 0, NN * sizeof(int), s2);
    cudaMemsetAsync(pcr, 0, NN * sizeof(int), s2);
    cudaMemsetAsync(pff, 0, NN * sizeof(int), s2);
    cudaMemsetAsync(pfr, 0, NN * sizeof(int), s2);
    k_count<<<(NE + 255) / 256, 256, 0, s2>>>(ei);
    k_deg<<<(NN + 255) / 256, 256, 0, s2>>>();
    k_place<<<(NE + 255) / 256, 256, 0, s2>>>(ei);
    cudaEventRecord(evCSR, s2);

    // ---- main: both encoders (tensor-core), then layers ----
    k_encI<<<N_INST / 64, 128>>>(x, e1W, e1b, e2W, e2b, out);
    k_encN<<<(N_NETN + 63) / 64, 128>>>(xnet, n1W, n1b, n2W, n2b, out);

    k_mmt<<<(NN + 127) / 128, 256>>>(out, 0, convW, convb, reW, reb);
    cudaStreamWaitEvent(0, evCSR, 0);
    k_agg<<<NN / 8, 256>>>(convr, rer, lng, lnb, out, 64);

    for (int l = 1; l < 3; l++) {
        k_mmt<<<(NN + 127) / 128, 256>>>(
            out, l * 64,
            convW + l * 4096, convb + l * 64,
            reW + l * 4096,   reb + l * 64);
        k_agg<<<NN / 8, 256>>>(convr + l * 64, rer + l * 64,
                               lng + l * 64, lnb + l * 64,
                               out, (l + 1) * 64);
    }
}

// round 16
// speedup vs baseline: 1.0366x; 1.0366x over previous
#include <cuda_runtime.h>
#include <cuda_fp16.h>

#define N_INST 200000
#define N_NETN 50000
#define NN     250000
#define NE     2000000
#define NSCANB 245   // ceil(250000/1024)

// ---------------- device scratch (no runtime allocation allowed) ----------------
__device__ float   g_xf[(size_t)NN * 64];     // x_f = h @ Wf + bf (fp32, self term)
__device__ float   g_xr[(size_t)NN * 64];     // x_r = h @ Wr + br
__device__ __half2 g_yf[(size_t)NN * 32];     // relu(x_f) fp16 (gather payload)
__device__ __half2 g_yr[(size_t)NN * 32];     // relu(x_r) fp16
__device__ float   g_tmpn[(size_t)N_NETN * 64]; // encoder hidden (net)
__device__ float   g_disf[NN], g_disr[NN];    // deg^-1/2
__device__ float   g_idegf[NN], g_idegr[NN];  // deg^-1
__device__ int     g_cntf[NN], g_cntr[NN];    // edge counts (row / col)
__device__ int     g_offF[NN], g_offR[NN];    // CSR bucket starts
__device__ int     g_fillF[NN], g_fillR[NN];
__device__ int     g_bsF[256], g_bsR[256];    // scan block sums
__device__ int2    g_csrF[NE];                // (src, norm) bucketed by col
__device__ int2    g_csrR[NE];                // (src, norm) bucketed by row

// ---------------- helpers ----------------
__device__ __forceinline__ float leaky(float v) { return fmaxf(v, 0.1f * v); }

__device__ __forceinline__ unsigned long long dup64(float a) {
    unsigned long long r;
    asm("mov.b64 %0, {%1, %1};" : "=l"(r) : "f"(a));
    return r;
}
__device__ __forceinline__ float2 up64(unsigned long long v) {
    float2 r;
    asm("mov.b64 {%0, %1}, %2;" : "=f"(r.x), "=f"(r.y) : "l"(v));
    return r;
}
__device__ __forceinline__ void fma2(unsigned long long& d,
                                     unsigned long long a,
                                     unsigned long long b) {
    asm("fma.rn.f32x2 %0, %1, %2, %0;" : "+l"(d) : "l"(a), "l"(b));
}
__device__ __forceinline__ void ldsm4(unsigned& r0, unsigned& r1, unsigned& r2,
                                      unsigned& r3, unsigned a) {
    asm volatile("ldmatrix.sync.aligned.m8n8.x4.shared.b16 {%0,%1,%2,%3}, [%4];"
                 : "=r"(r0), "=r"(r1), "=r"(r2), "=r"(r3) : "r"(a));
}
__device__ __forceinline__ void ldsm4t(unsigned& r0, unsigned& r1, unsigned& r2,
                                       unsigned& r3, unsigned a) {
    asm volatile("ldmatrix.sync.aligned.m8n8.x4.trans.shared.b16 {%0,%1,%2,%3}, [%4];"
                 : "=r"(r0), "=r"(r1), "=r"(r2), "=r"(r3) : "r"(a));
}
__device__ __forceinline__ void mma16816(float* c, unsigned a0, unsigned a1,
                                         unsigned a2, unsigned a3,
                                         unsigned b0, unsigned b1) {
    asm volatile(
        "mma.sync.aligned.m16n8k16.row.col.f32.f16.f16.f32 "
        "{%0,%1,%2,%3}, {%4,%5,%6,%7}, {%8,%9}, {%0,%1,%2,%3};"
        : "+f"(c[0]), "+f"(c[1]), "+f"(c[2]), "+f"(c[3])
        : "r"(a0), "r"(a1), "r"(a2), "r"(a3), "r"(b0), "r"(b1));
}

// ---------------- degree counting ----------------
__global__ __launch_bounds__(256) void k_count(const int* __restrict__ ei) {
    int e = blockIdx.x * 256 + threadIdx.x;
    if (e >= NE) return;
    atomicAdd(&g_cntf[ei[e]], 1);
    atomicAdd(&g_cntr[ei[NE + e]], 1);
}

__global__ __launch_bounds__(256) void k_deg() {
    int n = blockIdx.x * 256 + threadIdx.x;
    if (n >= NN) return;
    float df = (float)g_cntf[n] + 1.0f;
    float dr = (float)g_cntr[n] + 1.0f;
    g_disf[n] = rsqrtf(df);
    g_disr[n] = rsqrtf(dr);
    g_idegf[n] = 1.0f / df;
    g_idegr[n] = 1.0f / dr;
}

// ---------------- exclusive scan ----------------
__global__ __launch_bounds__(256) void k_scan1(const int* __restrict__ cnt,
                                               int* __restrict__ off,
                                               int* __restrict__ bsum) {
    __shared__ int wsum[8];
    int tid = threadIdx.x, lane = tid & 31, w = tid >> 5;
    int base = blockIdx.x * 1024 + tid * 4;
    int v0 = (base + 0 < NN) ? cnt[base + 0] : 0;
    int v1 = (base + 1 < NN) ? cnt[base + 1] : 0;
    int v2 = (base + 2 < NN) ? cnt[base + 2] : 0;
    int v3 = (base + 3 < NN) ? cnt[base + 3] : 0;
    int s = v0 + v1 + v2 + v3;
    int x = s;
#pragma unroll
    for (int o = 1; o < 32; o <<= 1) {
        int y = __shfl_up_sync(0xffffffffu, x, o);
        if (lane >= o) x += y;
    }
    if (lane == 31) wsum[w] = x;
    __syncthreads();
    if (tid == 0) {
        int r = 0;
#pragma unroll
        for (int j = 0; j < 8; j++) { int t = wsum[j]; wsum[j] = r; r += t; }
        bsum[blockIdx.x] = r;
    }
    __syncthreads();
    int ex = wsum[w] + x - s;
    if (base + 0 < NN) off[base + 0] = ex;
    if (base + 1 < NN) off[base + 1] = ex + v0;
    if (base + 2 < NN) off[base + 2] = ex + v0 + v1;
    if (base + 3 < NN) off[base + 3] = ex + v0 + v1 + v2;
}

__global__ __launch_bounds__(256) void k_scan2(int* __restrict__ bsum, int nb) {
    __shared__ int sm[256];
    int tid = threadIdx.x;
    int v = (tid < nb) ? bsum[tid] : 0;
    sm[tid] = v;
    __syncthreads();
#pragma unroll
    for (int o = 1; o < 256; o <<= 1) {
        int t = (tid >= o) ? sm[tid - o] : 0;
        __syncthreads();
        sm[tid] += t;
        __syncthreads();
    }
    if (tid < nb) bsum[tid] = sm[tid] - v;
}

__global__ __launch_bounds__(256) void k_scan3(int* __restrict__ off,
                                               const int* __restrict__ bsum) {
    int add = bsum[blockIdx.x];
    int base = blockIdx.x * 1024 + threadIdx.x * 4;
#pragma unroll
    for (int i = 0; i < 4; i++)
        if (base + i < NN) off[base + i] += add;
}

// ---------------- CSR placement, split per direction ----------------
__global__ __launch_bounds__(256) void k_placeF(const int* __restrict__ ei) {
    int e = blockIdx.x * 256 + threadIdx.x;
    if (e >= NE) return;
    int a = __ldg(ei + e);
    int b = __ldg(ei + NE + e);
    float nf = __ldg(&g_disf[a]) * __ldg(&g_disf[b]);
    int pf = g_offF[b] + atomicAdd(&g_fillF[b], 1);
    g_csrF[pf] = make_int2(a, __float_as_int(nf));
}

__global__ __launch_bounds__(256) void k_placeR(const int* __restrict__ ei) {
    int e = blockIdx.x * 256 + threadIdx.x;
    if (e >= NE) return;
    int a = __ldg(ei + e);
    int b = __ldg(ei + NE + e);
    float nr = __ldg(&g_disr[b]) * __ldg(&g_disr[a]);
    int pr = g_offR[a] + atomicAdd(&g_fillR[a], 1);
    g_csrR[pr] = make_int2(b, __float_as_int(nr));
}

// ---------------- encoder stage 1 (net only) ----------------
template<int KIN, int KOUT, int NPB>
__global__ __launch_bounds__(256) void k_encA(
    const float* __restrict__ x, const float* __restrict__ W,
    const float* __restrict__ bias, float* __restrict__ tmp, int nNodes)
{
    __shared__ float xs[NPB * KIN];
    int tid = threadIdx.x;
    int base = blockIdx.x * NPB;
    const int NSUB = 256 / KOUT;
#pragma unroll
    for (int i = 0; i < (NPB * KIN + 255) / 256; i++) {
        int idx = tid + i * 256;
        if (idx < NPB * KIN) {
            size_t gidx = (size_t)base * KIN + idx;
            size_t mx = (size_t)nNodes * KIN - 1;
            xs[idx] = x[gidx <= mx ? gidx : mx];
        }
    }
    int j = tid & (KOUT - 1);
    int nsub = tid / KOUT;
    float wcol[KIN];
#pragma unroll
    for (int k = 0; k < KIN; k++) wcol[k] = W[k * KOUT + j];
    float bj = bias[j];
    __syncthreads();
#pragma unroll
    for (int t = 0; t < NPB / NSUB; t++) {
        int n = nsub + t * NSUB;
        float a = bj;
#pragma unroll
        for (int k4 = 0; k4 < KIN; k4 += 4) {
            float4 xv = *(const float4*)&xs[n * KIN + k4];
            a += xv.x * wcol[k4] + xv.y * wcol[k4 + 1]
               + xv.z * wcol[k4 + 2] + xv.w * wcol[k4 + 3];
        }
        if (base + n < nNodes)
            tmp[(size_t)(base + n) * KOUT + j] = leaky(a);
    }
}

// ---------------- register-tiled GEMM (net encoder stage 2) ----------------
template<int KTOT, bool LEAKY>
__global__ __launch_bounds__(128) void k_mm(
    const float* __restrict__ src, int srcStride, int srcOff, int srcBase,
    const float* __restrict__ W, const float* __restrict__ bias,
    float* __restrict__ dst, int dstStride, int dstOff, int dstBase,
    int nNodes)
{
    __shared__ float hs[64 * 68];
    __shared__ float ws[32 * 64];
    int tid = threadIdx.x;
    int tb = blockIdx.x * 64;
    int tx = tid & 15, ty = tid >> 4;
    int bn = ty * 8;
    unsigned long long acc[4][4];
#pragma unroll
    for (int a = 0; a < 4; a++)
#pragma unroll
        for (int b = 0; b < 4; b++) acc[a][b] = 0ull;

    int c = tid & 63, r = tid >> 6;
    for (int kc = 0; kc < KTOT; kc += 64) {
        if (kc) __syncthreads();
#pragma unroll
        for (int i = 0; i < 32; i++) {
            int nl = i * 2 + r;
            int g = tb + nl; if (g >= nNodes) g = nNodes - 1;
            hs[c * 68 + nl] = src[(size_t)(srcBase + g) * srcStride + srcOff + kc + c];
        }
#pragma unroll
        for (int kk = 0; kk < 64; kk += 32) {
            __syncthreads();
#pragma unroll
            for (int i = 0; i < 16; i++)
                ws[tid + i * 128] = W[(kc + kk) * 64 + tid + i * 128];
            __syncthreads();
#pragma unroll 4
            for (int k = 0; k < 32; k++) {
                float4 wf = *(const float4*)&ws[k * 64 + tx * 4];
                unsigned long long dw0 = dup64(wf.x);
                unsigned long long dw1 = dup64(wf.y);
                unsigned long long dw2 = dup64(wf.z);
                unsigned long long dw3 = dup64(wf.w);
                ulonglong2 hA = *(const ulonglong2*)&hs[(kk + k) * 68 + bn];
                ulonglong2 hB = *(const ulonglong2*)&hs[(kk + k) * 68 + bn + 4];
                fma2(acc[0][0], hA.x, dw0); fma2(acc[0][1], hA.x, dw1);
                fma2(acc[0][2], hA.x, dw2); fma2(acc[0][3], hA.x, dw3);
                fma2(acc[1][0], hA.y, dw0); fma2(acc[1][1], hA.y, dw1);
                fma2(acc[1][2], hA.y, dw2); fma2(acc[1][3], hA.y, dw3);
                fma2(acc[2][0], hB.x, dw0); fma2(acc[2][1], hB.x, dw1);
                fma2(acc[2][2], hB.x, dw2); fma2(acc[2][3], hB.x, dw3);
                fma2(acc[3][0], hB.y, dw0); fma2(acc[3][1], hB.y, dw1);
                fma2(acc[3][2], hB.y, dw2); fma2(acc[3][3], hB.y, dw3);
            }
        }
    }
    float4 bv = *(const float4*)&bias[tx * 4];
#pragma unroll
    for (int np = 0; np < 4; np++) {
        int n0 = tb + bn + np * 2;
        float2 v0 = up64(acc[np][0]);
        float2 v1 = up64(acc[np][1]);
        float2 v2 = up64(acc[np][2]);
        float2 v3 = up64(acc[np][3]);
        float4 o0 = make_float4(v0.x + bv.x, v1.x + bv.y, v2.x + bv.z, v3.x + bv.w);
        float4 o1 = make_float4(v0.y + bv.x, v1.y + bv.y, v2.y + bv.z, v3.y + bv.w);
        if (LEAKY) {
            o0 = make_float4(leaky(o0.x), leaky(o0.y), leaky(o0.z), leaky(o0.w));
            o1 = make_float4(leaky(o1.x), leaky(o1.y), leaky(o1.z), leaky(o1.w));
        }
        if (n0 < nNodes)
            *(float4*)&dst[(size_t)(dstBase + n0) * dstStride + dstOff + tx * 4] = o0;
        if (n0 + 1 < nNodes)
            *(float4*)&dst[(size_t)(dstBase + n0 + 1) * dstStride + dstOff + tx * 4] = o1;
    }
}

// ---------------- fused tensor-core instance encoder (stage-1 v2: W1 in regs) ----------------
__global__ __launch_bounds__(128) void k_encI(
    const float* __restrict__ x,
    const float* __restrict__ W1, const float* __restrict__ b1,
    const float* __restrict__ W2, const float* __restrict__ b2,
    float* __restrict__ out)
{
    __shared__ float  xs[64 * 16];
    __shared__ float  W1s[16 * 128];
    __shared__ float  b1s[128];
    __shared__ __half sT[64 * 128];    // row 256 B, swizzle ((c*2)^((n&7)<<4))
    __shared__ __half sW2[128 * 64];   // row 128 B, swizzle ((o*2)^((k&7)<<4))
    int tid = threadIdx.x;
    int tb = blockIdx.x * 64;

#pragma unroll
    for (int i = 0; i < 2; i++)
        ((float4*)xs)[tid + i * 128] = ((const float4*)(x + (size_t)tb * 16))[tid + i * 128];
#pragma unroll
    for (int i = 0; i < 4; i++)
        ((float4*)W1s)[tid + i * 128] = ((const float4*)W1)[tid + i * 128];
    if (tid < 128) b1s[tid] = b1[tid];
    {
        int o2 = (tid & 31) * 2;
        int k0 = tid >> 5;
#pragma unroll
        for (int i = 0; i < 32; i++) {
            int k = k0 + i * 4;
            float2 v = *(const float2*)&W2[k * 64 + o2];
            *(__half2*)((char*)sW2 + k * 128 + ((o2 * 2) ^ ((k & 7) << 4))) =
                __float22half2_rn(v);
        }
    }
    __syncthreads();

    // stage 1 v2: thread owns output column j = tid; W1 column in registers,
    // x rows broadcast from smem. Same accumulation order as before (k ascending).
    {
        float wcol[16];
#pragma unroll
        for (int k = 0; k < 16; k++) wcol[k] = W1s[k * 128 + tid];
        float bj = b1s[tid];
        int sw = tid * 2;
#pragma unroll 4
        for (int n = 0; n < 64; n++) {
            float a = bj;
#pragma unroll
            for (int k4 = 0; k4 < 16; k4 += 4) {
                float4 xv = *(const float4*)&xs[n * 16 + k4];
                a += xv.x * wcol[k4] + xv.y * wcol[k4 + 1]
                   + xv.z * wcol[k4 + 2] + xv.w * wcol[k4 + 3];
            }
            __half h = __float2half_rn(leaky(a));
            int byte = n * 256 + (sw ^ ((n & 7) << 4));
            *(__half*)((char*)sT + byte) = h;
        }
    }
    __syncthreads();

    unsigned tBase = (unsigned)__cvta_generic_to_shared(sT);
    unsigned wBase = (unsigned)__cvta_generic_to_shared(sW2);
    int w = tid >> 5, lane = tid & 31;
    int bn = w * 16;
    int g = lane >> 3, r = lane & 7;
    int tr = lane >> 2, tc = lane & 3;
    float c[8][4];
#pragma unroll
    for (int j = 0; j < 8; j++)
#pragma unroll
        for (int q = 0; q < 4; q++) c[j][q] = 0.f;
#pragma unroll
    for (int ks = 0; ks < 8; ks++) {
        int mrow = bn + (g & 1) * 8 + r;
        int kc = ks * 16 + (g >> 1) * 8;
        unsigned a0, a1, a2, a3;
        ldsm4(a0, a1, a2, a3, tBase + mrow * 256 + ((kc * 2) ^ ((mrow & 7) << 4)));
        int kb = ks * 16 + (g & 1) * 8 + r;
        unsigned bofs = wBase + kb * 128;
#pragma unroll
        for (int otp = 0; otp < 4; otp++) {
            int oc = otp * 16 + (g >> 1) * 8;
            unsigned b0, b1_, b2_, b3;
            ldsm4t(b0, b1_, b2_, b3, bofs + ((oc * 2) ^ ((kb & 7) << 4)));
            mma16816(c[otp * 2],     a0, a1, a2, a3, b0, b1_);
            mma16816(c[otp * 2 + 1], a0, a1, a2, a3, b2_, b3);
        }
    }
    int n0 = tb + bn + tr;
    int n1 = n0 + 8;
#pragma unroll
    for (int j = 0; j < 8; j++) {
        int o = j * 8 + tc * 2;
        float2 bv = *(const float2*)&b2[o];
        float2 e0 = make_float2(leaky(c[j][0] + bv.x), leaky(c[j][1] + bv.y));
        float2 e1 = make_float2(leaky(c[j][2] + bv.x), leaky(c[j][3] + bv.y));
        *(float2*)&out[(size_t)n0 * 256 + o] = e0;
        *(float2*)&out[(size_t)n1 * 256 + o] = e1;
    }
}

// ---------------- tensor-core fused dual conv GEMM ----------------
__global__ __launch_bounds__(256) void k_mmt(
    const float* __restrict__ src, int srcOff,
    const float* __restrict__ Wf, const float* __restrict__ bf,
    const float* __restrict__ Wr, const float* __restrict__ br)
{
    __shared__ __half sA[128 * 64];
    __shared__ __half sW[2 * 64 * 64];
    int tid = threadIdx.x;
    int tb = blockIdx.x * 128;

    {
        int c2 = (tid & 31) * 2;
        int n0 = tid >> 5;
#pragma unroll
        for (int i = 0; i < 16; i++) {
            int n = n0 + i * 8;
            int g = tb + n; if (g >= NN) g = NN - 1;
            float2 v = *(const float2*)&src[(size_t)g * 256 + srcOff + c2];
            int byte = n * 128 + ((c2 * 2) ^ ((n & 7) << 4));
            *(__half2*)((char*)sA + byte) = __float22half2_rn(v);
        }
    }
    {
        int o2 = (tid & 31) * 2;
        int k0 = tid >> 5;
#pragma unroll
        for (int i = 0; i < 8; i++) {
            int k = k0 + i * 8;
            float2 vf = *(const float2*)&Wf[k * 64 + o2];
            float2 vr = *(const float2*)&Wr[k * 64 + o2];
            int sw = k * 128 + ((o2 * 2) ^ ((k & 7) << 4));
            *(__half2*)((char*)sW + sw) = __float22half2_rn(vf);
            *(__half2*)((char*)sW + 8192 + sw) = __float22half2_rn(vr);
        }
    }
    __syncthreads();

    unsigned aBase = (unsigned)__cvta_generic_to_shared(sA);
    unsigned wBase = (unsigned)__cvta_generic_to_shared(sW);
    int w = tid >> 5, lane = tid & 31;
    int bn = w * 16;
    int g = lane >> 3, r = lane & 7;
    int tr = lane >> 2, tc = lane & 3;

#pragma unroll
    for (int dir = 0; dir < 2; dir++) {
        const float* bias = dir ? br : bf;
        float*       dst  = dir ? g_xr : g_xf;
        __half2*     yout = dir ? g_yr : g_yf;
        float c[8][4];
#pragma unroll
        for (int j = 0; j < 8; j++)
#pragma unroll
            for (int q = 0; q < 4; q++) c[j][q] = 0.f;

#pragma unroll
        for (int ks = 0; ks < 4; ks++) {
            int mrow = bn + (g & 1) * 8 + r;
            int kc = ks * 16 + (g >> 1) * 8;
            unsigned a0, a1, a2, a3;
            ldsm4(a0, a1, a2, a3,
                  aBase + mrow * 128 + (((kc * 2)) ^ ((mrow & 7) << 4)));
            int kb = ks * 16 + (g & 1) * 8 + r;
            unsigned bofs = wBase + dir * 8192 + kb * 128;
#pragma unroll
            for (int otp = 0; otp < 4; otp++) {
                int oc = otp * 16 + (g >> 1) * 8;
                unsigned b0, b1, b2, b3;
                ldsm4t(b0, b1, b2, b3, bofs + ((oc * 2) ^ ((kb & 7) << 4)));
                mma16816(c[otp * 2],     a0, a1, a2, a3, b0, b1);
                mma16816(c[otp * 2 + 1], a0, a1, a2, a3, b2, b3);
            }
        }
        int n0 = tb + bn + tr;
        int n1 = n0 + 8;
#pragma unroll
        for (int j = 0; j < 8; j++) {
            int o = j * 8 + tc * 2;
            float2 bv = *(const float2*)&bias[o];
            float2 e0 = make_float2(c[j][0] + bv.x, c[j][1] + bv.y);
            float2 e1 = make_float2(c[j][2] + bv.x, c[j][3] + bv.y);
            if (n0 < NN) {
                *(float2*)&dst[(size_t)n0 * 64 + o] = e0;
                yout[(size_t)n0 * 32 + (o >> 1)] =
                    __float22half2_rn(make_float2(fmaxf(e0.x, 0.f), fmaxf(e0.y, 0.f)));
            }
            if (n1 < NN) {
                *(float2*)&dst[(size_t)n1 * 64 + o] = e1;
                yout[(size_t)n1 * 32 + (o >> 1)] =
                    __float22half2_rn(make_float2(fmaxf(e1.x, 0.f), fmaxf(e1.y, 0.f)));
            }
        }
    }
}

// ---------------- fused aggregation (R12 form) + self terms + LayerNorm + leaky ----------------
__global__ __launch_bounds__(256) void k_agg(
    const float* __restrict__ rootf, const float* __restrict__ rootr,
    const float* __restrict__ lg, const float* __restrict__ lb,
    float* __restrict__ out, int off)
{
    int n = blockIdx.x * 8 + (threadIdx.x >> 5);
    int lane = threadIdx.x & 31;
    int d = lane * 2;
    int begF = g_offF[n], degF = g_cntr[n];
    int begR = g_offR[n], degR = g_cntf[n];
    float2 af = make_float2(0.f, 0.f);
    float2 ar = make_float2(0.f, 0.f);
    {
        const int2* cs = g_csrF + begF;
        const __half2* Y = g_yf;
        int i = 0;
        for (; i + 4 <= degF; i += 4) {
            int2 e0 = __ldg(cs + i), e1 = __ldg(cs + i + 1);
            int2 e2 = __ldg(cs + i + 2), e3 = __ldg(cs + i + 3);
            float2 v0 = __half22float2(__ldg(Y + (size_t)e0.x * 32 + lane));
            float2 v1 = __half22float2(__ldg(Y + (size_t)e1.x * 32 + lane));
            float2 v2 = __half22float2(__ldg(Y + (size_t)e2.x * 32 + lane));
            float2 v3 = __half22float2(__ldg(Y + (size_t)e3.x * 32 + lane));
            float n0 = __int_as_float(e0.y), n1 = __int_as_float(e1.y);
            float n2 = __int_as_float(e2.y), n3 = __int_as_float(e3.y);
            af.x += v0.x * n0 + v1.x * n1 + v2.x * n2 + v3.x * n3;
            af.y += v0.y * n0 + v1.y * n1 + v2.y * n2 + v3.y * n3;
        }
        for (; i < degF; i++) {
            int2 e0 = __ldg(cs + i);
            float2 v0 = __half22float2(__ldg(Y + (size_t)e0.x * 32 + lane));
            float n0 = __int_as_float(e0.y);
            af.x += v0.x * n0;
            af.y += v0.y * n0;
        }
    }
    {
        const int2* cs = g_csrR + begR;
        const __half2* Y = g_yr;
        int i = 0;
        for (; i + 4 <= degR; i += 4) {
            int2 e0 = __ldg(cs + i), e1 = __ldg(cs + i + 1);
            int2 e2 = __ldg(cs + i + 2), e3 = __ldg(cs + i + 3);
            float2 v0 = __half22float2(__ldg(Y + (size_t)e0.x * 32 + lane));
            float2 v1 = __half22float2(__ldg(Y + (size_t)e1.x * 32 + lane));
            float2 v2 = __half22float2(__ldg(Y + (size_t)e2.x * 32 + lane));
            float2 v3 = __half22float2(__ldg(Y + (size_t)e3.x * 32 + lane));
            float n0 = __int_as_float(e0.y), n1 = __int_as_float(e1.y);
            float n2 = __int_as_float(e2.y), n3 = __int_as_float(e3.y);
            ar.x += v0.x * n0 + v1.x * n1 + v2.x * n2 + v3.x * n3;
            ar.y += v0.y * n0 + v1.y * n1 + v2.y * n2 + v3.y * n3;
        }
        for (; i < degR; i++) {
            int2 e0 = __ldg(cs + i);
            float2 v0 = __half22float2(__ldg(Y + (size_t)e0.x * 32 + lane));
            float n0 = __int_as_float(e0.y);
            ar.x += v0.x * n0;
            ar.y += v0.y * n0;
        }
    }
    size_t o64 = (size_t)n * 64 + d;
    float2 fx = *(const float2*)&g_xf[o64];
    float2 rx = *(const float2*)&g_xr[o64];
    float idf = g_idegf[n], idr = g_idegr[n];
    float s0 = af.x + ar.x + fmaxf(fx.x + rootf[d], 0.f) * idf
                           + fmaxf(rx.x + rootr[d], 0.f) * idr;
    float s1 = af.y + ar.y + fmaxf(fx.y + rootf[d + 1], 0.f) * idf
                           + fmaxf(rx.y + rootr[d + 1], 0.f) * idr;
    float sum = s0 + s1;
#pragma unroll
    for (int o = 16; o > 0; o >>= 1) sum += __shfl_xor_sync(0xffffffffu, sum, o);
    float m = sum * (1.0f / 64.0f);
    float d0 = s0 - m, d1 = s1 - m;
    float sq = d0 * d0 + d1 * d1;
#pragma unroll
    for (int o = 16; o > 0; o >>= 1) sq += __shfl_xor_sync(0xffffffffu, sq, o);
    float inv = rsqrtf(sq * (1.0f / 64.0f) + 1e-5f);
    float o0 = leaky(d0 * inv * lg[d] + lb[d]);
    float o1 = leaky(d1 * inv * lg[d + 1] + lb[d + 1]);
    *(float2*)&out[(size_t)n * 256 + off + d] = make_float2(o0, o1);
}

// ---------------- launch ----------------
extern "C" void kernel_launch(void* const* d_in, const int* in_sizes, int n_in,
                              void* d_out, int out_size) {
    const float* x     = (const float*)d_in[0];
    const float* xnet  = (const float*)d_in[1];
    const int*   ei    = (const int*)  d_in[2];
    const float* e1W   = (const float*)d_in[3];
    const float* e1b   = (const float*)d_in[4];
    const float* e2W   = (const float*)d_in[5];
    const float* e2b   = (const float*)d_in[6];
    const float* n1W   = (const float*)d_in[7];
    const float* n1b   = (const float*)d_in[8];
    const float* n2W   = (const float*)d_in[9];
    const float* n2b   = (const float*)d_in[10];
    const float* convW = (const float*)d_in[11];
    const float* convb = (const float*)d_in[12];
    const float* convr = (const float*)d_in[13];
    const float* reW   = (const float*)d_in[14];
    const float* reb   = (const float*)d_in[15];
    const float* rer   = (const float*)d_in[16];
    const float* lng   = (const float*)d_in[17];
    const float* lnb   = (const float*)d_in[18];
    float* out = (float*)d_out;

    void *pcf, *pcr, *pff, *pfr, *poF, *poR, *pbF, *pbR, *ptmpn;
    cudaGetSymbolAddress(&pcf, g_cntf);
    cudaGetSymbolAddress(&pcr, g_cntr);
    cudaGetSymbolAddress(&pff, g_fillF);
    cudaGetSymbolAddress(&pfr, g_fillR);
    cudaGetSymbolAddress(&poF, g_offF);
    cudaGetSymbolAddress(&poR, g_offR);
    cudaGetSymbolAddress(&pbF, g_bsF);
    cudaGetSymbolAddress(&pbR, g_bsR);
    cudaGetSymbolAddress(&ptmpn, g_tmpn);

    static cudaStream_t s2 = []() {
        cudaStream_t s; cudaStreamCreateWithFlags(&s, cudaStreamNonBlocking); return s;
    }();
    static cudaStream_t s3 = []() {
        cudaStream_t s; cudaStreamCreateWithFlags(&s, cudaStreamNonBlocking); return s;
    }();
    static cudaStream_t s4 = []() {
        cudaStream_t s; cudaStreamCreateWithFlags(&s, cudaStreamNonBlocking); return s;
    }();
    auto mkev = []() { cudaEvent_t e; cudaEventCreateWithFlags(&e, cudaEventDisableTiming); return e; };
    static cudaEvent_t evF = mkev();
    static cudaEvent_t evDeg = mkev();
    static cudaEvent_t evCSRF = mkev();
    static cudaEvent_t evCSRR = mkev();
    static cudaEvent_t evNet = mkev();

    cudaEventRecord(evF, 0);

    // ---- s2: degrees, then forward CSR chain ----
    cudaStreamWaitEvent(s2, evF, 0);
    cudaMemsetAsync(pcf, 0, NN * sizeof(int), s2);
    cudaMemsetAsync(pcr, 0, NN * sizeof(int), s2);
    cudaMemsetAsync(pff, 0, NN * sizeof(int), s2);
    cudaMemsetAsync(pfr, 0, NN * sizeof(int), s2);
    k_count<<<(NE + 255) / 256, 256, 0, s2>>>(ei);
    k_deg<<<(NN + 255) / 256, 256, 0, s2>>>();
    cudaEventRecord(evDeg, s2);
    k_scan1<<<NSCANB, 256, 0, s2>>>((const int*)pcr, (int*)poF, (int*)pbF);
    k_scan2<<<1, 256, 0, s2>>>((int*)pbF, NSCANB);
    k_scan3<<<NSCANB, 256, 0, s2>>>((int*)poF, (const int*)pbF);
    k_placeF<<<(NE + 255) / 256, 256, 0, s2>>>(ei);
    cudaEventRecord(evCSRF, s2);

    // ---- s4: reverse CSR chain (parallel with forward) ----
    cudaStreamWaitEvent(s4, evDeg, 0);
    k_scan1<<<NSCANB, 256, 0, s4>>>((const int*)pcf, (int*)poR, (int*)pbR);
    k_scan2<<<1, 256, 0, s4>>>((int*)pbR, NSCANB);
    k_scan3<<<NSCANB, 256, 0, s4>>>((int*)poR, (const int*)pbR);
    k_placeR<<<(NE + 255) / 256, 256, 0, s4>>>(ei);
    cudaEventRecord(evCSRR, s4);

    // ---- s3: net encoder ----
    cudaStreamWaitEvent(s3, evF, 0);
    k_encA<8, 64, 32><<<(N_NETN + 31) / 32, 256, 0, s3>>>(
        xnet, n1W, n1b, (float*)ptmpn, N_NETN);
    k_mm<64, true><<<(N_NETN + 63) / 64, 128, 0, s3>>>(
        (const float*)ptmpn, 64, 0, 0, n2W, n2b, out, 256, 0, N_INST, N_NETN);
    cudaEventRecord(evNet, s3);

    // ---- main: fused tensor-core instance encoder ----
    k_encI<<<N_INST / 64, 128>>>(x, e1W, e1b, e2W, e2b, out);

    // ---- layer 0: mmt needs only encoders; agg needs CSR too ----
    cudaStreamWaitEvent(0, evNet, 0);
    k_mmt<<<(NN + 127) / 128, 256>>>(out, 0, convW, convb, reW, reb);
    cudaStreamWaitEvent(0, evCSRF, 0);
    cudaStreamWaitEvent(0, evCSRR, 0);
    k_agg<<<NN / 8, 256>>>(convr, rer, lng, lnb, out, 64);

    // ---- layers 1,2 ----
    for (int l = 1; l < 3; l++) {
        k_mmt<<<(NN + 127) / 128, 256>>>(
            out, l * 64,
            convW + l * 4096, convb + l * 64,
            reW + l * 4096,   reb + l * 64);
        k_agg<<<NN / 8, 256>>>(convr + l * 64, rer + l * 64,
                               lng + l * 64, lnb + l * 64,
                               out, (l + 1) * 64);
    }
}

// round 17
// speedup vs baseline: 1.0791x; 1.0410x over previous
#include <cuda_runtime.h>
#include <cuda_fp16.h>

#define N_INST 200000
#define N_NETN 50000
#define NN     250000
#define NE     2000000
#define NSCANB 245   // ceil(250000/1024)

// ---------------- device scratch (no runtime allocation allowed) ----------------
__device__ float   g_self[(size_t)NN * 64];   // combined self terms (fp32)
__device__ __half2 g_yf[(size_t)NN * 32];     // relu(x_f) fp16 (gather payload)
__device__ __half2 g_yr[(size_t)NN * 32];     // relu(x_r) fp16
__device__ float   g_tmpn[(size_t)N_NETN * 64]; // encoder hidden (net)
__device__ float   g_disf[NN], g_disr[NN];    // deg^-1/2
__device__ float   g_idegf[NN], g_idegr[NN];  // deg^-1
__device__ int     g_cntf[NN], g_cntr[NN];    // edge counts (row / col)
__device__ int     g_offF[NN], g_offR[NN];    // CSR bucket starts
__device__ int     g_fillF[NN], g_fillR[NN];
__device__ int     g_bsF[256], g_bsR[256];    // scan block sums
__device__ int2    g_csrF[NE];                // (src, norm) bucketed by col
__device__ int2    g_csrR[NE];                // (src, norm) bucketed by row

// ---------------- helpers ----------------
__device__ __forceinline__ float leaky(float v) { return fmaxf(v, 0.1f * v); }

__device__ __forceinline__ unsigned long long dup64(float a) {
    unsigned long long r;
    asm("mov.b64 %0, {%1, %1};" : "=l"(r) : "f"(a));
    return r;
}
__device__ __forceinline__ float2 up64(unsigned long long v) {
    float2 r;
    asm("mov.b64 {%0, %1}, %2;" : "=f"(r.x), "=f"(r.y) : "l"(v));
    return r;
}
__device__ __forceinline__ void fma2(unsigned long long& d,
                                     unsigned long long a,
                                     unsigned long long b) {
    asm("fma.rn.f32x2 %0, %1, %2, %0;" : "+l"(d) : "l"(a), "l"(b));
}
__device__ __forceinline__ void ldsm4(unsigned& r0, unsigned& r1, unsigned& r2,
                                      unsigned& r3, unsigned a) {
    asm volatile("ldmatrix.sync.aligned.m8n8.x4.shared.b16 {%0,%1,%2,%3}, [%4];"
                 : "=r"(r0), "=r"(r1), "=r"(r2), "=r"(r3) : "r"(a));
}
__device__ __forceinline__ void ldsm4t(unsigned& r0, unsigned& r1, unsigned& r2,
                                       unsigned& r3, unsigned a) {
    asm volatile("ldmatrix.sync.aligned.m8n8.x4.trans.shared.b16 {%0,%1,%2,%3}, [%4];"
                 : "=r"(r0), "=r"(r1), "=r"(r2), "=r"(r3) : "r"(a));
}
__device__ __forceinline__ void mma16816(float* c, unsigned a0, unsigned a1,
                                         unsigned a2, unsigned a3,
                                         unsigned b0, unsigned b1) {
    asm volatile(
        "mma.sync.aligned.m16n8k16.row.col.f32.f16.f16.f32 "
        "{%0,%1,%2,%3}, {%4,%5,%6,%7}, {%8,%9}, {%0,%1,%2,%3};"
        : "+f"(c[0]), "+f"(c[1]), "+f"(c[2]), "+f"(c[3])
        : "r"(a0), "r"(a1), "r"(a2), "r"(a3), "r"(b0), "r"(b1));
}

// ---------------- degree counting ----------------
__global__ __launch_bounds__(256) void k_count(const int* __restrict__ ei) {
    int e = blockIdx.x * 256 + threadIdx.x;
    if (e >= NE) return;
    atomicAdd(&g_cntf[ei[e]], 1);
    atomicAdd(&g_cntr[ei[NE + e]], 1);
}

__global__ __launch_bounds__(256) void k_deg() {
    int n = blockIdx.x * 256 + threadIdx.x;
    if (n >= NN) return;
    float df = (float)g_cntf[n] + 1.0f;
    float dr = (float)g_cntr[n] + 1.0f;
    g_disf[n] = rsqrtf(df);
    g_disr[n] = rsqrtf(dr);
    g_idegf[n] = 1.0f / df;
    g_idegr[n] = 1.0f / dr;
}

// ---------------- exclusive scan ----------------
__global__ __launch_bounds__(256) void k_scan1(const int* __restrict__ cnt,
                                               int* __restrict__ off,
                                               int* __restrict__ bsum) {
    __shared__ int wsum[8];
    int tid = threadIdx.x, lane = tid & 31, w = tid >> 5;
    int base = blockIdx.x * 1024 + tid * 4;
    int v0 = (base + 0 < NN) ? cnt[base + 0] : 0;
    int v1 = (base + 1 < NN) ? cnt[base + 1] : 0;
    int v2 = (base + 2 < NN) ? cnt[base + 2] : 0;
    int v3 = (base + 3 < NN) ? cnt[base + 3] : 0;
    int s = v0 + v1 + v2 + v3;
    int x = s;
#pragma unroll
    for (int o = 1; o < 32; o <<= 1) {
        int y = __shfl_up_sync(0xffffffffu, x, o);
        if (lane >= o) x += y;
    }
    if (lane == 31) wsum[w] = x;
    __syncthreads();
    if (tid == 0) {
        int r = 0;
#pragma unroll
        for (int j = 0; j < 8; j++) { int t = wsum[j]; wsum[j] = r; r += t; }
        bsum[blockIdx.x] = r;
    }
    __syncthreads();
    int ex = wsum[w] + x - s;
    if (base + 0 < NN) off[base + 0] = ex;
    if (base + 1 < NN) off[base + 1] = ex + v0;
    if (base + 2 < NN) off[base + 2] = ex + v0 + v1;
    if (base + 3 < NN) off[base + 3] = ex + v0 + v1 + v2;
}

__global__ __launch_bounds__(256) void k_scan2(int* __restrict__ bsum, int nb) {
    __shared__ int sm[256];
    int tid = threadIdx.x;
    int v = (tid < nb) ? bsum[tid] : 0;
    sm[tid] = v;
    __syncthreads();
#pragma unroll
    for (int o = 1; o < 256; o <<= 1) {
        int t = (tid >= o) ? sm[tid - o] : 0;
        __syncthreads();
        sm[tid] += t;
        __syncthreads();
    }
    if (tid < nb) bsum[tid] = sm[tid] - v;
}

__global__ __launch_bounds__(256) void k_scan3(int* __restrict__ off,
                                               const int* __restrict__ bsum) {
    int add = bsum[blockIdx.x];
    int base = blockIdx.x * 1024 + threadIdx.x * 4;
#pragma unroll
    for (int i = 0; i < 4; i++)
        if (base + i < NN) off[base + i] += add;
}

// ---------------- CSR placement, split per direction ----------------
__global__ __launch_bounds__(256) void k_placeF(const int* __restrict__ ei) {
    int e = blockIdx.x * 256 + threadIdx.x;
    if (e >= NE) return;
    int a = __ldg(ei + e);
    int b = __ldg(ei + NE + e);
    float nf = __ldg(&g_disf[a]) * __ldg(&g_disf[b]);
    int pf = g_offF[b] + atomicAdd(&g_fillF[b], 1);
    g_csrF[pf] = make_int2(a, __float_as_int(nf));
}

__global__ __launch_bounds__(256) void k_placeR(const int* __restrict__ ei) {
    int e = blockIdx.x * 256 + threadIdx.x;
    if (e >= NE) return;
    int a = __ldg(ei + e);
    int b = __ldg(ei + NE + e);
    float nr = __ldg(&g_disr[b]) * __ldg(&g_disr[a]);
    int pr = g_offR[a] + atomicAdd(&g_fillR[a], 1);
    g_csrR[pr] = make_int2(b, __float_as_int(nr));
}

// ---------------- encoder stage 1 (net only) ----------------
template<int KIN, int KOUT, int NPB>
__global__ __launch_bounds__(256) void k_encA(
    const float* __restrict__ x, const float* __restrict__ W,
    const float* __restrict__ bias, float* __restrict__ tmp, int nNodes)
{
    __shared__ float xs[NPB * KIN];
    int tid = threadIdx.x;
    int base = blockIdx.x * NPB;
    const int NSUB = 256 / KOUT;
#pragma unroll
    for (int i = 0; i < (NPB * KIN + 255) / 256; i++) {
        int idx = tid + i * 256;
        if (idx < NPB * KIN) {
            size_t gidx = (size_t)base * KIN + idx;
            size_t mx = (size_t)nNodes * KIN - 1;
            xs[idx] = x[gidx <= mx ? gidx : mx];
        }
    }
    int j = tid & (KOUT - 1);
    int nsub = tid / KOUT;
    float wcol[KIN];
#pragma unroll
    for (int k = 0; k < KIN; k++) wcol[k] = W[k * KOUT + j];
    float bj = bias[j];
    __syncthreads();
#pragma unroll
    for (int t = 0; t < NPB / NSUB; t++) {
        int n = nsub + t * NSUB;
        float a = bj;
#pragma unroll
        for (int k4 = 0; k4 < KIN; k4 += 4) {
            float4 xv = *(const float4*)&xs[n * KIN + k4];
            a += xv.x * wcol[k4] + xv.y * wcol[k4 + 1]
               + xv.z * wcol[k4 + 2] + xv.w * wcol[k4 + 3];
        }
        if (base + n < nNodes)
            tmp[(size_t)(base + n) * KOUT + j] = leaky(a);
    }
}

// ---------------- register-tiled GEMM (net encoder stage 2) ----------------
template<int KTOT, bool LEAKY>
__global__ __launch_bounds__(128) void k_mm(
    const float* __restrict__ src, int srcStride, int srcOff, int srcBase,
    const float* __restrict__ W, const float* __restrict__ bias,
    float* __restrict__ dst, int dstStride, int dstOff, int dstBase,
    int nNodes)
{
    __shared__ float hs[64 * 68];
    __shared__ float ws[32 * 64];
    int tid = threadIdx.x;
    int tb = blockIdx.x * 64;
    int tx = tid & 15, ty = tid >> 4;
    int bn = ty * 8;
    unsigned long long acc[4][4];
#pragma unroll
    for (int a = 0; a < 4; a++)
#pragma unroll
        for (int b = 0; b < 4; b++) acc[a][b] = 0ull;

    int c = tid & 63, r = tid >> 6;
    for (int kc = 0; kc < KTOT; kc += 64) {
        if (kc) __syncthreads();
#pragma unroll
        for (int i = 0; i < 32; i++) {
            int nl = i * 2 + r;
            int g = tb + nl; if (g >= nNodes) g = nNodes - 1;
            hs[c * 68 + nl] = src[(size_t)(srcBase + g) * srcStride + srcOff + kc + c];
        }
#pragma unroll
        for (int kk = 0; kk < 64; kk += 32) {
            __syncthreads();
#pragma unroll
            for (int i = 0; i < 16; i++)
                ws[tid + i * 128] = W[(kc + kk) * 64 + tid + i * 128];
            __syncthreads();
#pragma unroll 4
            for (int k = 0; k < 32; k++) {
                float4 wf = *(const float4*)&ws[k * 64 + tx * 4];
                unsigned long long dw0 = dup64(wf.x);
                unsigned long long dw1 = dup64(wf.y);
                unsigned long long dw2 = dup64(wf.z);
                unsigned long long dw3 = dup64(wf.w);
                ulonglong2 hA = *(const ulonglong2*)&hs[(kk + k) * 68 + bn];
                ulonglong2 hB = *(const ulonglong2*)&hs[(kk + k) * 68 + bn + 4];
                fma2(acc[0][0], hA.x, dw0); fma2(acc[0][1], hA.x, dw1);
                fma2(acc[0][2], hA.x, dw2); fma2(acc[0][3], hA.x, dw3);
                fma2(acc[1][0], hA.y, dw0); fma2(acc[1][1], hA.y, dw1);
                fma2(acc[1][2], hA.y, dw2); fma2(acc[1][3], hA.y, dw3);
                fma2(acc[2][0], hB.x, dw0); fma2(acc[2][1], hB.x, dw1);
                fma2(acc[2][2], hB.x, dw2); fma2(acc[2][3], hB.x, dw3);
                fma2(acc[3][0], hB.y, dw0); fma2(acc[3][1], hB.y, dw1);
                fma2(acc[3][2], hB.y, dw2); fma2(acc[3][3], hB.y, dw3);
            }
        }
    }
    float4 bv = *(const float4*)&bias[tx * 4];
#pragma unroll
    for (int np = 0; np < 4; np++) {
        int n0 = tb + bn + np * 2;
        float2 v0 = up64(acc[np][0]);
        float2 v1 = up64(acc[np][1]);
        float2 v2 = up64(acc[np][2]);
        float2 v3 = up64(acc[np][3]);
        float4 o0 = make_float4(v0.x + bv.x, v1.x + bv.y, v2.x + bv.z, v3.x + bv.w);
        float4 o1 = make_float4(v0.y + bv.x, v1.y + bv.y, v2.y + bv.z, v3.y + bv.w);
        if (LEAKY) {
            o0 = make_float4(leaky(o0.x), leaky(o0.y), leaky(o0.z), leaky(o0.w));
            o1 = make_float4(leaky(o1.x), leaky(o1.y), leaky(o1.z), leaky(o1.w));
        }
        if (n0 < nNodes)
            *(float4*)&dst[(size_t)(dstBase + n0) * dstStride + dstOff + tx * 4] = o0;
        if (n0 + 1 < nNodes)
            *(float4*)&dst[(size_t)(dstBase + n0 + 1) * dstStride + dstOff + tx * 4] = o1;
    }
}

// ---------------- fused tensor-core instance encoder ----------------
__global__ __launch_bounds__(128) void k_encI(
    const float* __restrict__ x,
    const float* __restrict__ W1, const float* __restrict__ b1,
    const float* __restrict__ W2, const float* __restrict__ b2,
    float* __restrict__ out)
{
    __shared__ float  xs[64 * 16];
    __shared__ float  W1s[16 * 128];
    __shared__ float  b1s[128];
    __shared__ __half sT[64 * 128];
    __shared__ __half sW2[128 * 64];
    int tid = threadIdx.x;
    int tb = blockIdx.x * 64;

#pragma unroll
    for (int i = 0; i < 2; i++)
        ((float4*)xs)[tid + i * 128] = ((const float4*)(x + (size_t)tb * 16))[tid + i * 128];
#pragma unroll
    for (int i = 0; i < 4; i++)
        ((float4*)W1s)[tid + i * 128] = ((const float4*)W1)[tid + i * 128];
    if (tid < 128) b1s[tid] = b1[tid];
    {
        int o2 = (tid & 31) * 2;
        int k0 = tid >> 5;
#pragma unroll
        for (int i = 0; i < 32; i++) {
            int k = k0 + i * 4;
            float2 v = *(const float2*)&W2[k * 64 + o2];
            *(__half2*)((char*)sW2 + k * 128 + ((o2 * 2) ^ ((k & 7) << 4))) =
                __float22half2_rn(v);
        }
    }
    __syncthreads();

    {
        float wcol[16];
#pragma unroll
        for (int k = 0; k < 16; k++) wcol[k] = W1s[k * 128 + tid];
        float bj = b1s[tid];
        int sw = tid * 2;
#pragma unroll 4
        for (int n = 0; n < 64; n++) {
            float a = bj;
#pragma unroll
            for (int k4 = 0; k4 < 16; k4 += 4) {
                float4 xv = *(const float4*)&xs[n * 16 + k4];
                a += xv.x * wcol[k4] + xv.y * wcol[k4 + 1]
                   + xv.z * wcol[k4 + 2] + xv.w * wcol[k4 + 3];
            }
            __half h = __float2half_rn(leaky(a));
            int byte = n * 256 + (sw ^ ((n & 7) << 4));
            *(__half*)((char*)sT + byte) = h;
        }
    }
    __syncthreads();

    unsigned tBase = (unsigned)__cvta_generic_to_shared(sT);
    unsigned wBase = (unsigned)__cvta_generic_to_shared(sW2);
    int w = tid >> 5, lane = tid & 31;
    int bn = w * 16;
    int g = lane >> 3, r = lane & 7;
    int tr = lane >> 2, tc = lane & 3;
    float c[8][4];
#pragma unroll
    for (int j = 0; j < 8; j++)
#pragma unroll
        for (int q = 0; q < 4; q++) c[j][q] = 0.f;
#pragma unroll
    for (int ks = 0; ks < 8; ks++) {
        int mrow = bn + (g & 1) * 8 + r;
        int kc = ks * 16 + (g >> 1) * 8;
        unsigned a0, a1, a2, a3;
        ldsm4(a0, a1, a2, a3, tBase + mrow * 256 + ((kc * 2) ^ ((mrow & 7) << 4)));
        int kb = ks * 16 + (g & 1) * 8 + r;
        unsigned bofs = wBase + kb * 128;
#pragma unroll
        for (int otp = 0; otp < 4; otp++) {
            int oc = otp * 16 + (g >> 1) * 8;
            unsigned b0, b1_, b2_, b3;
            ldsm4t(b0, b1_, b2_, b3, bofs + ((oc * 2) ^ ((kb & 7) << 4)));
            mma16816(c[otp * 2],     a0, a1, a2, a3, b0, b1_);
            mma16816(c[otp * 2 + 1], a0, a1, a2, a3, b2_, b3);
        }
    }
    int n0 = tb + bn + tr;
    int n1 = n0 + 8;
#pragma unroll
    for (int j = 0; j < 8; j++) {
        int o = j * 8 + tc * 2;
        float2 bv = *(const float2*)&b2[o];
        float2 e0 = make_float2(leaky(c[j][0] + bv.x), leaky(c[j][1] + bv.y));
        float2 e1 = make_float2(leaky(c[j][2] + bv.x), leaky(c[j][3] + bv.y));
        *(float2*)&out[(size_t)n0 * 256 + o] = e0;
        *(float2*)&out[(size_t)n1 * 256 + o] = e1;
    }
}

// ---------------- tensor-core fused dual conv GEMM + self-term epilogue ----------------
__global__ __launch_bounds__(256) void k_mmt(
    const float* __restrict__ src, int srcOff,
    const float* __restrict__ Wf, const float* __restrict__ bf,
    const float* __restrict__ Wr, const float* __restrict__ br,
    const float* __restrict__ rootf, const float* __restrict__ rootr)
{
    __shared__ __half sA[128 * 64];
    __shared__ __half sW[2 * 64 * 64];
    int tid = threadIdx.x;
    int tb = blockIdx.x * 128;

    {
        int c2 = (tid & 31) * 2;
        int n0 = tid >> 5;
#pragma unroll
        for (int i = 0; i < 16; i++) {
            int n = n0 + i * 8;
            int g = tb + n; if (g >= NN) g = NN - 1;
            float2 v = *(const float2*)&src[(size_t)g * 256 + srcOff + c2];
            int byte = n * 128 + ((c2 * 2) ^ ((n & 7) << 4));
            *(__half2*)((char*)sA + byte) = __float22half2_rn(v);
        }
    }
    {
        int o2 = (tid & 31) * 2;
        int k0 = tid >> 5;
#pragma unroll
        for (int i = 0; i < 8; i++) {
            int k = k0 + i * 8;
            float2 vf = *(const float2*)&Wf[k * 64 + o2];
            float2 vr = *(const float2*)&Wr[k * 64 + o2];
            int sw = k * 128 + ((o2 * 2) ^ ((k & 7) << 4));
            *(__half2*)((char*)sW + sw) = __float22half2_rn(vf);
            *(__half2*)((char*)sW + 8192 + sw) = __float22half2_rn(vr);
        }
    }
    __syncthreads();

    unsigned aBase = (unsigned)__cvta_generic_to_shared(sA);
    unsigned wBase = (unsigned)__cvta_generic_to_shared(sW);
    int w = tid >> 5, lane = tid & 31;
    int bn = w * 16;
    int g = lane >> 3, r = lane & 7;
    int tr = lane >> 2, tc = lane & 3;

    float cf[8][4], cr[8][4];
#pragma unroll
    for (int j = 0; j < 8; j++)
#pragma unroll
        for (int q = 0; q < 4; q++) { cf[j][q] = 0.f; cr[j][q] = 0.f; }

#pragma unroll
    for (int ks = 0; ks < 4; ks++) {
        int mrow = bn + (g & 1) * 8 + r;
        int kc = ks * 16 + (g >> 1) * 8;
        unsigned a0, a1, a2, a3;
        ldsm4(a0, a1, a2, a3,
              aBase + mrow * 128 + (((kc * 2)) ^ ((mrow & 7) << 4)));
        int kb = ks * 16 + (g & 1) * 8 + r;
        unsigned bofsF = wBase + kb * 128;
#pragma unroll
        for (int otp = 0; otp < 4; otp++) {
            int oc = otp * 16 + (g >> 1) * 8;
            unsigned sw = (unsigned)((oc * 2) ^ ((kb & 7) << 4));
            unsigned b0, b1, b2, b3;
            ldsm4t(b0, b1, b2, b3, bofsF + sw);
            mma16816(cf[otp * 2],     a0, a1, a2, a3, b0, b1);
            mma16816(cf[otp * 2 + 1], a0, a1, a2, a3, b2, b3);
            ldsm4t(b0, b1, b2, b3, bofsF + 8192 + sw);
            mma16816(cr[otp * 2],     a0, a1, a2, a3, b0, b1);
            mma16816(cr[otp * 2 + 1], a0, a1, a2, a3, b2, b3);
        }
    }
    int n0 = tb + bn + tr;
    int n1 = n0 + 8;
    int cn0 = n0 < NN ? n0 : NN - 1;
    int cn1 = n1 < NN ? n1 : NN - 1;
    float idf0 = g_idegf[cn0], idr0 = g_idegr[cn0];
    float idf1 = g_idegf[cn1], idr1 = g_idegr[cn1];
#pragma unroll
    for (int j = 0; j < 8; j++) {
        int o = j * 8 + tc * 2;
        float2 bfv = *(const float2*)&bf[o];
        float2 brv = *(const float2*)&br[o];
        float2 rfv = *(const float2*)&rootf[o];
        float2 rrv = *(const float2*)&rootr[o];
        float ef0x = cf[j][0] + bfv.x, ef0y = cf[j][1] + bfv.y;
        float ef1x = cf[j][2] + bfv.x, ef1y = cf[j][3] + bfv.y;
        float er0x = cr[j][0] + brv.x, er0y = cr[j][1] + brv.y;
        float er1x = cr[j][2] + brv.x, er1y = cr[j][3] + brv.y;
        if (n0 < NN) {
            g_yf[(size_t)n0 * 32 + (o >> 1)] =
                __float22half2_rn(make_float2(fmaxf(ef0x, 0.f), fmaxf(ef0y, 0.f)));
            g_yr[(size_t)n0 * 32 + (o >> 1)] =
                __float22half2_rn(make_float2(fmaxf(er0x, 0.f), fmaxf(er0y, 0.f)));
            float2 s;
            s.x = fmaxf(ef0x + rfv.x, 0.f) * idf0 + fmaxf(er0x + rrv.x, 0.f) * idr0;
            s.y = fmaxf(ef0y + rfv.y, 0.f) * idf0 + fmaxf(er0y + rrv.y, 0.f) * idr0;
            __stcs((float2*)&g_self[(size_t)n0 * 64 + o], s);
        }
        if (n1 < NN) {
            g_yf[(size_t)n1 * 32 + (o >> 1)] =
                __float22half2_rn(make_float2(fmaxf(ef1x, 0.f), fmaxf(ef1y, 0.f)));
            g_yr[(size_t)n1 * 32 + (o >> 1)] =
                __float22half2_rn(make_float2(fmaxf(er1x, 0.f), fmaxf(er1y, 0.f)));
            float2 s;
            s.x = fmaxf(ef1x + rfv.x, 0.f) * idf1 + fmaxf(er1x + rrv.x, 0.f) * idr1;
            s.y = fmaxf(ef1y + rfv.y, 0.f) * idf1 + fmaxf(er1y + rrv.y, 0.f) * idr1;
            __stcs((float2*)&g_self[(size_t)n1 * 64 + o], s);
        }
    }
}

// ---------------- fused aggregation + precomputed self + LayerNorm + leaky ----------------
__global__ __launch_bounds__(256) void k_agg(
    const float* __restrict__ lg, const float* __restrict__ lb,
    float* __restrict__ out, int off)
{
    int n = blockIdx.x * 8 + (threadIdx.x >> 5);
    int lane = threadIdx.x & 31;
    int d = lane * 2;
    int begF = g_offF[n], degF = g_cntr[n];
    int begR = g_offR[n], degR = g_cntf[n];
    float2 af = make_float2(0.f, 0.f);
    float2 ar = make_float2(0.f, 0.f);
    {
        const int2* cs = g_csrF + begF;
        const __half2* Y = g_yf;
        int i = 0;
        for (; i + 4 <= degF; i += 4) {
            int2 e0 = __ldcs(cs + i), e1 = __ldcs(cs + i + 1);
            int2 e2 = __ldcs(cs + i + 2), e3 = __ldcs(cs + i + 3);
            float2 v0 = __half22float2(__ldg(Y + (size_t)e0.x * 32 + lane));
            float2 v1 = __half22float2(__ldg(Y + (size_t)e1.x * 32 + lane));
            float2 v2 = __half22float2(__ldg(Y + (size_t)e2.x * 32 + lane));
            float2 v3 = __half22float2(__ldg(Y + (size_t)e3.x * 32 + lane));
            float n0 = __int_as_float(e0.y), n1 = __int_as_float(e1.y);
            float n2 = __int_as_float(e2.y), n3 = __int_as_float(e3.y);
            af.x += v0.x * n0 + v1.x * n1 + v2.x * n2 + v3.x * n3;
            af.y += v0.y * n0 + v1.y * n1 + v2.y * n2 + v3.y * n3;
        }
        for (; i < degF; i++) {
            int2 e0 = __ldcs(cs + i);
            float2 v0 = __half22float2(__ldg(Y + (size_t)e0.x * 32 + lane));
            float n0 = __int_as_float(e0.y);
            af.x += v0.x * n0;
            af.y += v0.y * n0;
        }
    }
    {
        const int2* cs = g_csrR + begR;
        const __half2* Y = g_yr;
        int i = 0;
        for (; i + 4 <= degR; i += 4) {
            int2 e0 = __ldcs(cs + i), e1 = __ldcs(cs + i + 1);
            int2 e2 = __ldcs(cs + i + 2), e3 = __ldcs(cs + i + 3);
            float2 v0 = __half22float2(__ldg(Y + (size_t)e0.x * 32 + lane));
            float2 v1 = __half22float2(__ldg(Y + (size_t)e1.x * 32 + lane));
            float2 v2 = __half22float2(__ldg(Y + (size_t)e2.x * 32 + lane));
            float2 v3 = __half22float2(__ldg(Y + (size_t)e3.x * 32 + lane));
            float n0 = __int_as_float(e0.y), n1 = __int_as_float(e1.y);
            float n2 = __int_as_float(e2.y), n3 = __int_as_float(e3.y);
            ar.x += v0.x * n0 + v1.x * n1 + v2.x * n2 + v3.x * n3;
            ar.y += v0.y * n0 + v1.y * n1 + v2.y * n2 + v3.y * n3;
        }
        for (; i < degR; i++) {
            int2 e0 = __ldcs(cs + i);
            float2 v0 = __half22float2(__ldg(Y + (size_t)e0.x * 32 + lane));
            float n0 = __int_as_float(e0.y);
            ar.x += v0.x * n0;
            ar.y += v0.y * n0;
        }
    }
    float2 sf = __ldcs((const float2*)&g_self[(size_t)n * 64 + d]);
    float s0 = af.x + ar.x + sf.x;
    float s1 = af.y + ar.y + sf.y;
    float sum = s0 + s1;
#pragma unroll
    for (int o = 16; o > 0; o >>= 1) sum += __shfl_xor_sync(0xffffffffu, sum, o);
    float m = sum * (1.0f / 64.0f);
    float d0 = s0 - m, d1 = s1 - m;
    float sq = d0 * d0 + d1 * d1;
#pragma unroll
    for (int o = 16; o > 0; o >>= 1) sq += __shfl_xor_sync(0xffffffffu, sq, o);
    float inv = rsqrtf(sq * (1.0f / 64.0f) + 1e-5f);
    float o0 = leaky(d0 * inv * lg[d] + lb[d]);
    float o1 = leaky(d1 * inv * lg[d + 1] + lb[d + 1]);
    *(float2*)&out[(size_t)n * 256 + off + d] = make_float2(o0, o1);
}

// ---------------- launch ----------------
extern "C" void kernel_launch(void* const* d_in, const int* in_sizes, int n_in,
                              void* d_out, int out_size) {
    const float* x     = (const float*)d_in[0];
    const float* xnet  = (const float*)d_in[1];
    const int*   ei    = (const int*)  d_in[2];
    const float* e1W   = (const float*)d_in[3];
    const float* e1b   = (const float*)d_in[4];
    const float* e2W   = (const float*)d_in[5];
    const float* e2b   = (const float*)d_in[6];
    const float* n1W   = (const float*)d_in[7];
    const float* n1b   = (const float*)d_in[8];
    const float* n2W   = (const float*)d_in[9];
    const float* n2b   = (const float*)d_in[10];
    const float* convW = (const float*)d_in[11];
    const float* convb = (const float*)d_in[12];
    const float* convr = (const float*)d_in[13];
    const float* reW   = (const float*)d_in[14];
    const float* reb   = (const float*)d_in[15];
    const float* rer   = (const float*)d_in[16];
    const float* lng   = (const float*)d_in[17];
    const float* lnb   = (const float*)d_in[18];
    float* out = (float*)d_out;

    void *pcf, *pcr, *pff, *pfr, *poF, *poR, *pbF, *pbR, *ptmpn;
    cudaGetSymbolAddress(&pcf, g_cntf);
    cudaGetSymbolAddress(&pcr, g_cntr);
    cudaGetSymbolAddress(&pff, g_fillF);
    cudaGetSymbolAddress(&pfr, g_fillR);
    cudaGetSymbolAddress(&poF, g_offF);
    cudaGetSymbolAddress(&poR, g_offR);
    cudaGetSymbolAddress(&pbF, g_bsF);
    cudaGetSymbolAddress(&pbR, g_bsR);
    cudaGetSymbolAddress(&ptmpn, g_tmpn);

    static cudaStream_t s2 = []() {
        cudaStream_t s; cudaStreamCreateWithFlags(&s, cudaStreamNonBlocking); return s;
    }();
    static cudaStream_t s3 = []() {
        cudaStream_t s; cudaStreamCreateWithFlags(&s, cudaStreamNonBlocking); return s;
    }();
    static cudaStream_t s4 = []() {
        cudaStream_t s; cudaStreamCreateWithFlags(&s, cudaStreamNonBlocking); return s;
    }();
    auto mkev = []() { cudaEvent_t e; cudaEventCreateWithFlags(&e, cudaEventDisableTiming); return e; };
    static cudaEvent_t evF = mkev();
    static cudaEvent_t evDeg = mkev();
    static cudaEvent_t evCSRF = mkev();
    static cudaEvent_t evCSRR = mkev();
    static cudaEvent_t evNet = mkev();

    cudaEventRecord(evF, 0);

    // ---- s2: degrees, then forward CSR chain ----
    cudaStreamWaitEvent(s2, evF, 0);
    cudaMemsetAsync(pcf, 0, NN * sizeof(int), s2);
    cudaMemsetAsync(pcr, 0, NN * sizeof(int), s2);
    cudaMemsetAsync(pff, 0, NN * sizeof(int), s2);
    cudaMemsetAsync(pfr, 0, NN * sizeof(int), s2);
    k_count<<<(NE + 255) / 256, 256, 0, s2>>>(ei);
    k_deg<<<(NN + 255) / 256, 256, 0, s2>>>();
    cudaEventRecord(evDeg, s2);
    k_scan1<<<NSCANB, 256, 0, s2>>>((const int*)pcr, (int*)poF, (int*)pbF);
    k_scan2<<<1, 256, 0, s2>>>((int*)pbF, NSCANB);
    k_scan3<<<NSCANB, 256, 0, s2>>>((int*)poF, (const int*)pbF);
    k_placeF<<<(NE + 255) / 256, 256, 0, s2>>>(ei);
    cudaEventRecord(evCSRF, s2);

    // ---- s4: reverse CSR chain (parallel with forward) ----
    cudaStreamWaitEvent(s4, evDeg, 0);
    k_scan1<<<NSCANB, 256, 0, s4>>>((const int*)pcf, (int*)poR, (int*)pbR);
    k_scan2<<<1, 256, 0, s4>>>((int*)pbR, NSCANB);
    k_scan3<<<NSCANB, 256, 0, s4>>>((int*)poR, (const int*)pbR);
    k_placeR<<<(NE + 255) / 256, 256, 0, s4>>>(ei);
    cudaEventRecord(evCSRR, s4);

    // ---- s3: net encoder ----
    cudaStreamWaitEvent(s3, evF, 0);
    k_encA<8, 64, 32><<<(N_NETN + 31) / 32, 256, 0, s3>>>(
        xnet, n1W, n1b, (float*)ptmpn, N_NETN);
    k_mm<64, true><<<(N_NETN + 63) / 64, 128, 0, s3>>>(
        (const float*)ptmpn, 64, 0, 0, n2W, n2b, out, 256, 0, N_INST, N_NETN);
    cudaEventRecord(evNet, s3);

    // ---- main: fused tensor-core instance encoder ----
    k_encI<<<N_INST / 64, 128>>>(x, e1W, e1b, e2W, e2b, out);

    // ---- layer 0: mmt needs encoders + degrees; agg needs CSR too ----
    cudaStreamWaitEvent(0, evNet, 0);
    cudaStreamWaitEvent(0, evDeg, 0);
    k_mmt<<<(NN + 127) / 128, 256>>>(out, 0, convW, convb, reW, reb, convr, rer);
    cudaStreamWaitEvent(0, evCSRF, 0);
    cudaStreamWaitEvent(0, evCSRR, 0);
    k_agg<<<NN / 8, 256>>>(lng, lnb, out, 64);

    // ---- layers 1,2 ----
    for (int l = 1; l < 3; l++) {
        k_mmt<<<(NN + 127) / 128, 256>>>(
            out, l * 64,
            convW + l * 4096, convb + l * 64,
            reW + l * 4096,   reb + l * 64,
            convr + l * 64,   rer + l * 64);
        k_agg<<<NN / 8, 256>>>(lng + l * 64, lnb + l * 64, out, (l + 1) * 64);
    }
}